// round 10
// baseline (speedup 1.0000x reference)
#include <cuda_runtime.h>
#include <cuda_fp16.h>
#include <math.h>
#include <stdint.h>

#define BATCH 2
#define SEQ 1024
#define HID 4096
#define NH 32
#define NKV 2
#define HD 128
#define FFN 13696
#define QKV_DIM ((NH + 2*NKV)*HD)   // 4608
#define M_ROWS (BATCH*SEQ)          // 2048
#define EPSV 1e-5f
#define V_OFF ((NH+NKV)*HD)         // 4352
#define K_OFF (NH*HD)               // 4096
#define K2H (2*HID)
#define K2F (2*FFN)
#define LO_SCALE 4096.0f            // 2^12
#define LO_INV   2.44140625e-4f     // 2^-12

// ------------------------- scratch (device globals) -------------------------
__device__ float g_qkv[(size_t)M_ROWS * QKV_DIM];
__device__ float g_attnout[(size_t)M_ROWS * HID];
__device__ float g_hidden[(size_t)M_ROWS * HID];
__device__ float g_inter[(size_t)M_ROWS * 2 * FFN];
// fp16 weights, planar split [hi | lo*2^12]
__device__ __half g_wqkvh[(size_t)QKV_DIM * K2H];
__device__ __half g_woh[(size_t)HID * K2H];
__device__ __half g_w14h[(size_t)(2*FFN) * K2H];
__device__ __half g_w41h[(size_t)HID * K2F];
// fp16 single activations
__device__ __half g_xh[(size_t)M_ROWS * HID];
__device__ __half g_ah[(size_t)M_ROWS * HID];
__device__ __half g_yh[(size_t)M_ROWS * HID];
__device__ __half g_gh[(size_t)M_ROWS * FFN];

// ------------------------- PTX helpers -------------------------
__device__ __forceinline__ uint32_t smem_u32(const void* p) {
    uint32_t a;
    asm("{ .reg .u64 t; cvta.to.shared.u64 t, %1; cvt.u32.u64 %0, t; }" : "=r"(a) : "l"(p));
    return a;
}
__device__ __forceinline__ void cp16(uint32_t s, const void* g) {
    asm volatile("cp.async.cg.shared.global [%0], [%1], 16;" :: "r"(s), "l"(g));
}
__device__ __forceinline__ void ldsm4(uint32_t* r, uint32_t addr) {
    asm volatile("ldmatrix.sync.aligned.m8n8.x4.shared.b16 {%0,%1,%2,%3}, [%4];"
                 : "=r"(r[0]), "=r"(r[1]), "=r"(r[2]), "=r"(r[3]) : "r"(addr));
}
__device__ __forceinline__ void mma_f16(float* c, const uint32_t* a, uint32_t b0, uint32_t b1) {
    asm volatile(
        "mma.sync.aligned.m16n8k16.row.col.f32.f16.f16.f32 "
        "{%0,%1,%2,%3}, {%4,%5,%6,%7}, {%8,%9}, {%0,%1,%2,%3};"
        : "+f"(c[0]), "+f"(c[1]), "+f"(c[2]), "+f"(c[3])
        : "r"(a[0]), "r"(a[1]), "r"(a[2]), "r"(a[3]), "r"(b0), "r"(b1));
}

// ------------------------- misc helpers -------------------------
__device__ __forceinline__ float warp_sum(float v) {
#pragma unroll
    for (int o = 16; o > 0; o >>= 1) v += __shfl_xor_sync(0xffffffffu, v, o);
    return v;
}
// fp16 split with lo-plane scaled by 2^12 (keeps lo in fp16 normal range)
__device__ __forceinline__ void split4h_scaled(float4 v, uint2& hi, uint2& lo) {
    union { uint2 u; __half h[4]; } H, L;
    float f[4] = {v.x, v.y, v.z, v.w};
#pragma unroll
    for (int k = 0; k < 4; k++) {
        __half h = __float2half_rn(f[k]);
        H.h[k] = h;
        L.h[k] = __float2half_rn((f[k] - __half2float(h)) * LO_SCALE);
    }
    hi = H.u; lo = L.u;
}
__device__ __forceinline__ uint2 pack4h(float4 v) {
    union { uint2 u; __half h[4]; } H;
    H.h[0] = __float2half_rn(v.x); H.h[1] = __float2half_rn(v.y);
    H.h[2] = __float2half_rn(v.z); H.h[3] = __float2half_rn(v.w);
    return H.u;
}

// ------------------------- weight split kernel -------------------------
__global__ void split_planar_f16(const float* __restrict__ in,
                                 __half* __restrict__ out,
                                 long long n4, int kq) {
    long long i = (long long)blockIdx.x * blockDim.x + threadIdx.x;
    if (i >= n4) return;
    float4 v = ((const float4*)in)[i];
    uint2 hi, lo;
    split4h_scaled(v, hi, lo);
    long long n = i / kq;
    long long hidx = i + n * kq;
    ((uint2*)out)[hidx] = hi;
    ((uint2*)out)[hidx + kq] = lo;
}

// ------------------------- fused (add+)rmsnorm -> fp16 single -------------------------
__global__ void __launch_bounds__(256) fused_norm_kernel(
    const float* __restrict__ res, const float* __restrict__ x,
    const float* __restrict__ w, float* __restrict__ hid_out,
    __half* __restrict__ yh) {
    __shared__ __align__(16) float buf[HID];
    __shared__ float red[8];
    int row = blockIdx.x;
    size_t base = (size_t)row * HID;
    const float4* x4 = (const float4*)(x + base);
    const float4* r4 = res ? (const float4*)(res + base) : nullptr;
    float4* b4 = (float4*)buf;

    float ss = 0.f;
    for (int i = threadIdx.x; i < HID/4; i += 256) {
        float4 v = x4[i];
        if (r4) { float4 rr = r4[i]; v.x += rr.x; v.y += rr.y; v.z += rr.z; v.w += rr.w; }
        b4[i] = v;
        ss += v.x*v.x + v.y*v.y + v.z*v.z + v.w*v.w;
    }
    ss = warp_sum(ss);
    if ((threadIdx.x & 31) == 0) red[threadIdx.x >> 5] = ss;
    __syncthreads();
    float tot = 0.f;
#pragma unroll
    for (int i = 0; i < 8; i++) tot += red[i];
    float inv = rsqrtf(tot / (float)HID + EPSV);

    float4* h4 = hid_out ? (float4*)(hid_out + base) : nullptr;
    const float4* w4 = (const float4*)w;
    uint2* y2 = (uint2*)(yh + base);
    for (int i = threadIdx.x; i < HID/4; i += 256) {
        float4 v = b4[i];
        if (h4) h4[i] = v;
        float4 ww = w4[i];
        float4 o;
        o.x = v.x * inv * ww.x; o.y = v.y * inv * ww.y;
        o.z = v.z * inv * ww.z; o.w = v.w * inv * ww.w;
        y2[i] = pack4h(o);
    }
}

// ------------------------- fp16 2-phase HMMA GEMM, 4 warps x 64x64 -------------------------
// C[M,N] = A(fp16)[M,K] * (Bhi + Blo*2^-12)[N,K]^T (+bias)(+resid).
// B planar [hi | lo*2^12]; phase 0 = lo, fold acc *= 2^-12 at i==KC, phase 1 = hi.
// CTA tile 128x128, 128 threads = 4 warps (2m x 2n), warp tile 64x64.
// 3-stage cp.async pipeline, one __syncthreads per chunk, 2 CTA/SM.
#define NSTAGE 3
#define STAGE_BYTES 32768
#define GEMM_SMEM (NSTAGE * STAGE_BYTES + 1024)

__global__ void __launch_bounds__(128, 2) gemm_h(
    const __half* __restrict__ Av, const __half* __restrict__ Bv,
    const float* __restrict__ bias, const float* __restrict__ resid,
    float* __restrict__ C, int NT, int Kel, int N) {
    extern __shared__ char smem[];
    uint32_t dataA = (smem_u32(smem) + 1023) & ~1023u;
    int tid = threadIdx.x;
    int wid = tid >> 5, lane = tid & 31;

    // supertile rasterization: 16 m-tiles x 18 n-tiles
    int g = blockIdx.x / (16*18);
    int r = blockIdx.x % (16*18);
    int gn = NT - g*18; if (gn > 18) gn = 18;
    int bn = (g*18 + r % gn) * 128;
    int bm = (r / gn) * 128;

    const size_t rowbA = (size_t)Kel * 2;
    const size_t rowbB = (size_t)Kel * 4;
    const char* Abase = (const char*)Av + (size_t)bm * rowbA;
    const char* Bbase = (const char*)Bv + (size_t)bn * rowbB;
    const int KC = Kel >> 6;
    const int NC = 2 * KC;
    const int c16 = (tid & 7) * 16;
    const int row0 = tid >> 3;            // 0..15

    auto load_chunk = [&](int j) {
        // phase 0 = LO plane (scaled by 2^12), phase 1 = HI plane
        int phase = (j >= KC) ? 1 : 0;
        int jj = j - phase*KC;
        size_t a_byte = (size_t)jj * 128 + c16;
        size_t b_byte = ((size_t)(phase ? 0 : Kel) + (size_t)jj*64) * 2 + c16;
        int s = j % NSTAGE;
        uint32_t sA = dataA + s*STAGE_BYTES;
        uint32_t sB = sA + 16384;
#pragma unroll
        for (int p = 0; p < 8; p++) {
            int row = row0 + p*16;
            uint32_t sw = row*128 + (c16 ^ ((row & 7) << 4));
            cp16(sA + sw, Abase + (size_t)row * rowbA + a_byte);
            cp16(sB + sw, Bbase + (size_t)row * rowbB + b_byte);
        }
        asm volatile("cp.async.commit_group;" ::: "memory");
    };

    float acc[4][8][4];
#pragma unroll
    for (int a = 0; a < 4; a++)
#pragma unroll
        for (int b = 0; b < 8; b++)
#pragma unroll
            for (int c = 0; c < 4; c++) acc[a][b][c] = 0.f;

    const int warp_m = (wid & 1) * 64;    // 0, 64
    const int warp_n = (wid >> 1) * 64;   // 0, 64

    load_chunk(0);
    load_chunk(1);

    for (int i = 0; i < NC; i++) {
        asm volatile("cp.async.wait_group 1;" ::: "memory");
        __syncthreads();

        // LO -> HI transition: fold the 2^12 scale out of the accumulators
        if (i == KC) {
#pragma unroll
            for (int a = 0; a < 4; a++)
#pragma unroll
                for (int b = 0; b < 8; b++)
#pragma unroll
                    for (int c = 0; c < 4; c++) acc[a][b][c] *= LO_INV;
        }

        uint32_t sA = dataA + (i % NSTAGE)*STAGE_BYTES;
        uint32_t sB = sA + 16384;
#pragma unroll
        for (int ks = 0; ks < 4; ks++) {
            int kb = ks * 32;
            uint32_t af[4][4];
#pragma unroll
            for (int mt = 0; mt < 4; mt++) {
                int rw = warp_m + mt*16 + (lane & 15);
                int cb = kb + ((lane >> 4) << 4);
                ldsm4(af[mt], sA + rw*128 + (cb ^ ((rw & 7) << 4)));
            }
            uint32_t bf[4][4];
#pragma unroll
            for (int nt = 0; nt < 4; nt++) {
                int nr = warp_n + nt*16 + ((lane >> 4) << 3) + (lane & 7);
                int cb = kb + (((lane >> 3) & 1) << 4);
                ldsm4(bf[nt], sB + nr*128 + (cb ^ ((nr & 7) << 4)));
            }
#pragma unroll
            for (int mt = 0; mt < 4; mt++) {
#pragma unroll
                for (int nj = 0; nj < 8; nj++) {
                    const uint32_t* bb = bf[nj >> 1];
                    uint32_t b0 = (nj & 1) ? bb[2] : bb[0];
                    uint32_t b1 = (nj & 1) ? bb[3] : bb[1];
                    mma_f16(acc[mt][nj], af[mt], b0, b1);
                }
            }
        }
        if (i + 2 < NC) load_chunk(i + 2);
        else asm volatile("cp.async.commit_group;" ::: "memory");
    }

    // epilogue
#pragma unroll
    for (int mt = 0; mt < 4; mt++) {
        int row0g = bm + warp_m + mt*16 + (lane >> 2);
#pragma unroll
        for (int nj = 0; nj < 8; nj++) {
            int col = bn + warp_n + nj*8 + (lane & 3)*2;
            float b0 = 0.f, b1 = 0.f;
            if (bias) { b0 = bias[col]; b1 = bias[col+1]; }
            float* p0 = C + (size_t)row0g * N + col;
            float* p1 = C + (size_t)(row0g + 8) * N + col;
            float2 v0 = make_float2(acc[mt][nj][0] + b0, acc[mt][nj][1] + b1);
            float2 v1 = make_float2(acc[mt][nj][2] + b0, acc[mt][nj][3] + b1);
            if (resid) {
                float2 r0 = *(const float2*)(resid + (size_t)row0g * N + col);
                float2 r1 = *(const float2*)(resid + (size_t)(row0g + 8) * N + col);
                v0.x += r0.x; v0.y += r0.y; v1.x += r1.x; v1.y += r1.y;
            }
            *(float2*)p0 = v0;
            *(float2*)p1 = v1;
        }
    }
}

// ------------------------- RoPE (in-place on q,k of qkv) -------------------------
__global__ void rope_kernel(const int* __restrict__ positions, float* __restrict__ qkv) {
    int bs = blockIdx.x;
    int hh = blockIdx.y;
    int i  = threadIdx.x;
    float* base = qkv + (size_t)bs * QKV_DIM + hh * HD;
    float pos = (float)positions[bs];
    float freq = __expf(-(float)i * 0.14391565217f);
    float ang = pos * freq;
    float sn, cs;
    sincosf(ang, &sn, &cs);
    float x1 = base[i];
    float x2 = base[i + 64];
    base[i]      = x1 * cs - x2 * sn;
    base[i + 64] = x2 * cs + x1 * sn;
}

// ------------------------- flash attention (causal, GQA), fp16 ctx out ----
__global__ void __launch_bounds__(128) flash_attn_kernel(
    const float* __restrict__ qkv, __half* __restrict__ ah) {
    __shared__ __align__(16) float Qs[32][HD];
    __shared__ __align__(16) float KVs[32][HD];
    __shared__ float Ss[32][33];
    __shared__ float m_s[32], l_s[32], alpha_s[32];

    int qt = blockIdx.x;
    int h  = blockIdx.y;
    int b  = blockIdx.z;
    int kvh = h >> 4;
    int tid = threadIdx.x;
    int r  = tid >> 2;
    int qd = tid & 3;
    int q0 = qt * 32;

    for (int i = tid; i < 32*32; i += 128) {
        int row = i >> 5, c4 = i & 31;
        ((float4*)Qs[row])[c4] =
            *(const float4*)(qkv + (size_t)(b*SEQ + q0 + row) * QKV_DIM + h*HD + c4*4);
    }
    if (tid < 32) { m_s[tid] = -1e30f; l_s[tid] = 0.f; }
    float acc[32];
#pragma unroll
    for (int i = 0; i < 32; i++) acc[i] = 0.f;
    __syncthreads();

    const float scale = 0.08838834764831845f;

    for (int kt = 0; kt <= qt; kt++) {
        int k0 = kt * 32;
        for (int i = tid; i < 32*32; i += 128) {
            int row = i >> 5, c4 = i & 31;
            ((float4*)KVs[row])[c4] =
                *(const float4*)(qkv + (size_t)(b*SEQ + k0 + row) * QKV_DIM + K_OFF + kvh*HD + c4*4);
        }
        __syncthreads();

        int j0 = qd * 8;
        float sc[8];
#pragma unroll
        for (int jj = 0; jj < 8; jj++) sc[jj] = 0.f;
        const float4* q4 = (const float4*)Qs[r];
#pragma unroll 4
        for (int d4 = 0; d4 < 32; d4++) {
            float4 qv = q4[d4];
#pragma unroll
            for (int jj = 0; jj < 8; jj++) {
                float4 kv = ((const float4*)KVs[j0 + jj])[d4];
                sc[jj] += qv.x*kv.x + qv.y*kv.y + qv.z*kv.z + qv.w*kv.w;
            }
        }
#pragma unroll
        for (int jj = 0; jj < 8; jj++) {
            int kg = k0 + j0 + jj;
            Ss[r][j0 + jj] = (kg <= q0 + r) ? sc[jj] * scale : -1e30f;
        }
        __syncthreads();

        if (tid < 32) {
            float mx = m_s[tid];
            float tm = -1e30f;
#pragma unroll 8
            for (int j = 0; j < 32; j++) tm = fmaxf(tm, Ss[tid][j]);
            float mn = fmaxf(mx, tm);
            float al = __expf(mx - mn);
            float sum = 0.f;
#pragma unroll 8
            for (int j = 0; j < 32; j++) {
                float p = __expf(Ss[tid][j] - mn);
                Ss[tid][j] = p;
                sum += p;
            }
            m_s[tid] = mn;
            l_s[tid] = l_s[tid] * al + sum;
            alpha_s[tid] = al;
        }
        for (int i = tid; i < 32*32; i += 128) {
            int row = i >> 5, c4 = i & 31;
            ((float4*)KVs[row])[c4] =
                *(const float4*)(qkv + (size_t)(b*SEQ + k0 + row) * QKV_DIM + V_OFF + kvh*HD + c4*4);
        }
        __syncthreads();

        float al = alpha_s[r];
#pragma unroll
        for (int i = 0; i < 32; i++) acc[i] *= al;
#pragma unroll 4
        for (int j = 0; j < 32; j++) {
            float p = Ss[r][j];
            const float4* v4 = (const float4*)&KVs[j][qd*32];
#pragma unroll
            for (int i4 = 0; i4 < 8; i4++) {
                float4 vv = v4[i4];
                acc[i4*4+0] = fmaf(p, vv.x, acc[i4*4+0]);
                acc[i4*4+1] = fmaf(p, vv.y, acc[i4*4+1]);
                acc[i4*4+2] = fmaf(p, vv.z, acc[i4*4+2]);
                acc[i4*4+3] = fmaf(p, vv.w, acc[i4*4+3]);
            }
        }
        __syncthreads();
    }

    float invl = 1.f / l_s[r];
    uint2* o2 = (uint2*)(ah + (size_t)(b*SEQ + q0 + r) * HID + h*HD + qd*32);
#pragma unroll
    for (int i4 = 0; i4 < 8; i4++) {
        float4 o = make_float4(acc[i4*4+0]*invl, acc[i4*4+1]*invl,
                               acc[i4*4+2]*invl, acc[i4*4+3]*invl);
        o2[i4] = pack4h(o);
    }
}

// ------------------------- SwiGLU -> fp16 single -------------------------
__global__ void swiglu_h_kernel(const float* __restrict__ inter,
                                __half* __restrict__ gh) {
    int t = blockIdx.x * blockDim.x + threadIdx.x;
    if (t >= M_ROWS * (FFN/4)) return;
    int row = t / (FFN/4);
    int f4  = t - row * (FFN/4);
    const float* irow = inter + (size_t)row * (2*FFN);
    float4 a = *(const float4*)(irow + f4*4);
    float4 b = *(const float4*)(irow + FFN + f4*4);
    float4 o;
    o.x = (a.x / (1.f + __expf(-a.x))) * b.x;
    o.y = (a.y / (1.f + __expf(-a.y))) * b.y;
    o.z = (a.z / (1.f + __expf(-a.z))) * b.z;
    o.w = (a.w / (1.f + __expf(-a.w))) * b.w;
    ((uint2*)(gh + (size_t)row * FFN))[f4] = pack4h(o);
}

// ------------------------- launch -------------------------
extern "C" void kernel_launch(void* const* d_in, const int* in_sizes, int n_in,
                              void* d_out, int out_size) {
    const int*   positions = (const int*)d_in[0];
    const float* hs        = (const float*)d_in[1];
    const float* ln1       = (const float*)d_in[2];
    const float* wqkv      = (const float*)d_in[3];
    const float* bqkv      = (const float*)d_in[4];
    const float* wo        = (const float*)d_in[5];
    const float* ln2       = (const float*)d_in[6];
    const float* w14       = (const float*)d_in[7];
    const float* w41       = (const float*)d_in[8];
    float* out = (float*)d_out;

    float *qkv, *attnout, *hidden, *inter;
    __half *wqkvh, *woh, *w14h, *w41h, *xh, *ah, *yh, *gh;
    cudaGetSymbolAddress((void**)&qkv,     g_qkv);
    cudaGetSymbolAddress((void**)&attnout, g_attnout);
    cudaGetSymbolAddress((void**)&hidden,  g_hidden);
    cudaGetSymbolAddress((void**)&inter,   g_inter);
    cudaGetSymbolAddress((void**)&wqkvh,   g_wqkvh);
    cudaGetSymbolAddress((void**)&woh,     g_woh);
    cudaGetSymbolAddress((void**)&w14h,    g_w14h);
    cudaGetSymbolAddress((void**)&w41h,    g_w41h);
    cudaGetSymbolAddress((void**)&xh,      g_xh);
    cudaGetSymbolAddress((void**)&ah,      g_ah);
    cudaGetSymbolAddress((void**)&yh,      g_yh);
    cudaGetSymbolAddress((void**)&gh,      g_gh);

    cudaFuncSetAttribute(gemm_h, cudaFuncAttributeMaxDynamicSharedMemorySize, GEMM_SMEM);

    // weight splits (fp16 planar, lo scaled)
    {
        long long n4;
        n4 = (long long)QKV_DIM * HID / 4;
        split_planar_f16<<<(unsigned)((n4+255)/256), 256>>>(wqkv, wqkvh, n4, HID/4);
        n4 = (long long)HID * HID / 4;
        split_planar_f16<<<(unsigned)((n4+255)/256), 256>>>(wo, woh, n4, HID/4);
        n4 = (long long)(2*FFN) * HID / 4;
        split_planar_f16<<<(unsigned)((n4+255)/256), 256>>>(w14, w14h, n4, HID/4);
        n4 = (long long)HID * FFN / 4;
        split_planar_f16<<<(unsigned)((n4+255)/256), 256>>>(w41, w41h, n4, FFN/4);
    }

    // 1) xh = f16(rmsnorm(hs) * ln1)
    fused_norm_kernel<<<M_ROWS, 256>>>(nullptr, hs, ln1, nullptr, xh);

    // 2) qkv = x @ wqkv^T + bqkv
    gemm_h<<<16*36, 128, GEMM_SMEM>>>(xh, wqkvh, bqkv, nullptr, qkv, 36, HID, QKV_DIM);

    // 3) rope on q,k
    rope_kernel<<<dim3(M_ROWS, NH + NKV), 64>>>(positions, qkv);

    // 4) attention -> ah (fp16 ctx)
    flash_attn_kernel<<<dim3(SEQ/32, NH, BATCH), 128>>>(qkv, ah);

    // 5) attn_out = ctx @ wo^T
    gemm_h<<<16*32, 128, GEMM_SMEM>>>(ah, woh, nullptr, nullptr, attnout, 32, HID, HID);

    // 6) hidden = hs + attn_out ; yh = f16(rmsnorm(hidden) * ln2)
    fused_norm_kernel<<<M_ROWS, 256>>>(hs, attnout, ln2, hidden, yh);

    // 7) inter = y @ w14^T
    gemm_h<<<16*214, 128, GEMM_SMEM>>>(yh, w14h, nullptr, nullptr, inter, 214, HID, 2*FFN);

    // 8) gh = f16(silu(a)*b)
    swiglu_h_kernel<<<(M_ROWS*(FFN/4) + 255)/256, 256>>>(inter, gh);

    // 9) out = hidden + gated @ w41^T   (residual fused)
    gemm_h<<<16*32, 128, GEMM_SMEM>>>(gh, w41h, nullptr, hidden, out, 32, FFN, HID);
}

// round 11
// speedup vs baseline: 1.2472x; 1.2472x over previous
#include <cuda_runtime.h>
#include <cuda_fp16.h>
#include <math.h>
#include <stdint.h>

#define BATCH 2
#define SEQ 1024
#define HID 4096
#define NH 32
#define NKV 2
#define HD 128
#define FFN 13696
#define QKV_DIM ((NH + 2*NKV)*HD)   // 4608
#define M_ROWS (BATCH*SEQ)          // 2048
#define EPSV 1e-5f
#define V_OFF ((NH+NKV)*HD)         // 4352
#define K_OFF (NH*HD)               // 4096
#define K2H (2*HID)
#define LO_SCALE 4096.0f            // 2^12
#define LO_INV   2.44140625e-4f     // 2^-12

// ------------------------- scratch (device globals) -------------------------
__device__ float g_qkv[(size_t)M_ROWS * QKV_DIM];
__device__ float g_attnout[(size_t)M_ROWS * HID];
__device__ float g_hidden[(size_t)M_ROWS * HID];
__device__ float g_inter[(size_t)M_ROWS * 2 * FFN];
// fp16 weights: QKV/O planar split [hi | lo*2^12]; FFN single-plane fp16
__device__ __half g_wqkvh[(size_t)QKV_DIM * K2H];
__device__ __half g_woh[(size_t)HID * K2H];
__device__ __half g_w14h[(size_t)(2*FFN) * HID];
__device__ __half g_w41h[(size_t)HID * FFN];
// fp16 single activations
__device__ __half g_xh[(size_t)M_ROWS * HID];
__device__ __half g_ah[(size_t)M_ROWS * HID];
__device__ __half g_yh[(size_t)M_ROWS * HID];
__device__ __half g_gh[(size_t)M_ROWS * FFN];

// ------------------------- PTX helpers -------------------------
__device__ __forceinline__ uint32_t smem_u32(const void* p) {
    uint32_t a;
    asm("{ .reg .u64 t; cvta.to.shared.u64 t, %1; cvt.u32.u64 %0, t; }" : "=r"(a) : "l"(p));
    return a;
}
__device__ __forceinline__ void cp16(uint32_t s, const void* g) {
    asm volatile("cp.async.cg.shared.global [%0], [%1], 16;" :: "r"(s), "l"(g));
}
__device__ __forceinline__ void ldsm4(uint32_t* r, uint32_t addr) {
    asm volatile("ldmatrix.sync.aligned.m8n8.x4.shared.b16 {%0,%1,%2,%3}, [%4];"
                 : "=r"(r[0]), "=r"(r[1]), "=r"(r[2]), "=r"(r[3]) : "r"(addr));
}
__device__ __forceinline__ void mma_f16(float* c, const uint32_t* a, uint32_t b0, uint32_t b1) {
    asm volatile(
        "mma.sync.aligned.m16n8k16.row.col.f32.f16.f16.f32 "
        "{%0,%1,%2,%3}, {%4,%5,%6,%7}, {%8,%9}, {%0,%1,%2,%3};"
        : "+f"(c[0]), "+f"(c[1]), "+f"(c[2]), "+f"(c[3])
        : "r"(a[0]), "r"(a[1]), "r"(a[2]), "r"(a[3]), "r"(b0), "r"(b1));
}

// ------------------------- misc helpers -------------------------
__device__ __forceinline__ float warp_sum(float v) {
#pragma unroll
    for (int o = 16; o > 0; o >>= 1) v += __shfl_xor_sync(0xffffffffu, v, o);
    return v;
}
// fp16 split with lo-plane scaled by 2^12 (keeps lo in fp16 normal range)
__device__ __forceinline__ void split4h_scaled(float4 v, uint2& hi, uint2& lo) {
    union { uint2 u; __half h[4]; } H, L;
    float f[4] = {v.x, v.y, v.z, v.w};
#pragma unroll
    for (int k = 0; k < 4; k++) {
        __half h = __float2half_rn(f[k]);
        H.h[k] = h;
        L.h[k] = __float2half_rn((f[k] - __half2float(h)) * LO_SCALE);
    }
    hi = H.u; lo = L.u;
}
__device__ __forceinline__ uint2 pack4h(float4 v) {
    union { uint2 u; __half h[4]; } H;
    H.h[0] = __float2half_rn(v.x); H.h[1] = __float2half_rn(v.y);
    H.h[2] = __float2half_rn(v.z); H.h[3] = __float2half_rn(v.w);
    return H.u;
}

// ------------------------- weight conversion kernels -------------------------
__global__ void split_planar_f16(const float* __restrict__ in,
                                 __half* __restrict__ out,
                                 long long n4, int kq) {
    long long i = (long long)blockIdx.x * blockDim.x + threadIdx.x;
    if (i >= n4) return;
    float4 v = ((const float4*)in)[i];
    uint2 hi, lo;
    split4h_scaled(v, hi, lo);
    long long n = i / kq;
    long long hidx = i + n * kq;
    ((uint2*)out)[hidx] = hi;
    ((uint2*)out)[hidx + kq] = lo;
}
__global__ void round_f16_kernel(const float* __restrict__ in,
                                 __half* __restrict__ out, long long n4) {
    long long i = (long long)blockIdx.x * blockDim.x + threadIdx.x;
    if (i >= n4) return;
    ((uint2*)out)[i] = pack4h(((const float4*)in)[i]);
}

// ------------------------- fused (add+)rmsnorm -> fp16 single -------------------------
__global__ void __launch_bounds__(256) fused_norm_kernel(
    const float* __restrict__ res, const float* __restrict__ x,
    const float* __restrict__ w, float* __restrict__ hid_out,
    __half* __restrict__ yh) {
    __shared__ __align__(16) float buf[HID];
    __shared__ float red[8];
    int row = blockIdx.x;
    size_t base = (size_t)row * HID;
    const float4* x4 = (const float4*)(x + base);
    const float4* r4 = res ? (const float4*)(res + base) : nullptr;
    float4* b4 = (float4*)buf;

    float ss = 0.f;
    for (int i = threadIdx.x; i < HID/4; i += 256) {
        float4 v = x4[i];
        if (r4) { float4 rr = r4[i]; v.x += rr.x; v.y += rr.y; v.z += rr.z; v.w += rr.w; }
        b4[i] = v;
        ss += v.x*v.x + v.y*v.y + v.z*v.z + v.w*v.w;
    }
    ss = warp_sum(ss);
    if ((threadIdx.x & 31) == 0) red[threadIdx.x >> 5] = ss;
    __syncthreads();
    float tot = 0.f;
#pragma unroll
    for (int i = 0; i < 8; i++) tot += red[i];
    float inv = rsqrtf(tot / (float)HID + EPSV);

    float4* h4 = hid_out ? (float4*)(hid_out + base) : nullptr;
    const float4* w4 = (const float4*)w;
    uint2* y2 = (uint2*)(yh + base);
    for (int i = threadIdx.x; i < HID/4; i += 256) {
        float4 v = b4[i];
        if (h4) h4[i] = v;
        float4 ww = w4[i];
        float4 o;
        o.x = v.x * inv * ww.x; o.y = v.y * inv * ww.y;
        o.z = v.z * inv * ww.z; o.w = v.w * inv * ww.w;
        y2[i] = pack4h(o);
    }
}

// ------------------------- fp16 HMMA GEMM (R9 config, NPH phases) -------------------------
// NPH=2: B planar [hi | lo*2^12]; phase 0 = lo, fold acc *= 2^-12 at i==KC, phase 1 = hi.
// NPH=1: B single fp16 plane.
// Tile 128x128, chunk 64 elems, 256 thr = 8 warps (2m x 4n), 3-stage cp.async, 2 CTA/SM.
#define NSTAGE 3
#define STAGE_BYTES 32768
#define GEMM_SMEM (NSTAGE * STAGE_BYTES + 1024)

template<int NPH>
__global__ void __launch_bounds__(256, 2) gemm_h(
    const __half* __restrict__ Av, const __half* __restrict__ Bv,
    const float* __restrict__ bias, const float* __restrict__ resid,
    float* __restrict__ C, int NT, int Kel, int N) {
    extern __shared__ char smem[];
    uint32_t dataA = (smem_u32(smem) + 1023) & ~1023u;
    int tid = threadIdx.x;
    int wid = tid >> 5, lane = tid & 31;

    // supertile rasterization: 16 m-tiles x 18 n-tiles
    int g = blockIdx.x / (16*18);
    int r = blockIdx.x % (16*18);
    int gn = NT - g*18; if (gn > 18) gn = 18;
    int bn = (g*18 + r % gn) * 128;
    int bm = (r / gn) * 128;

    const size_t rowbA = (size_t)Kel * 2;
    const size_t rowbB = (size_t)Kel * 2 * NPH;
    const char* Abase = (const char*)Av + (size_t)bm * rowbA;
    const char* Bbase = (const char*)Bv + (size_t)bn * rowbB;
    const int KC = Kel >> 6;
    const int NC = NPH * KC;
    const int c16 = (tid & 7) * 16;
    const int row0 = tid >> 3;

    auto load_chunk = [&](int j) {
        size_t a_byte, b_byte;
        if (NPH == 2) {
            // phase 0 = LO plane (scaled by 2^12), phase 1 = HI plane
            int phase = (j >= KC) ? 1 : 0;
            int jj = j - phase*KC;
            a_byte = (size_t)jj * 128 + c16;
            b_byte = ((size_t)(phase ? 0 : Kel) + (size_t)jj*64) * 2 + c16;
        } else {
            a_byte = (size_t)j * 128 + c16;
            b_byte = (size_t)j * 128 + c16;
        }
        int s = j % NSTAGE;
        uint32_t sA = dataA + s*STAGE_BYTES;
        uint32_t sB = sA + 16384;
#pragma unroll
        for (int p = 0; p < 4; p++) {
            int row = row0 + p*32;
            uint32_t sw = row*128 + (c16 ^ ((row & 7) << 4));
            cp16(sA + sw, Abase + (size_t)row * rowbA + a_byte);
            cp16(sB + sw, Bbase + (size_t)row * rowbB + b_byte);
        }
        asm volatile("cp.async.commit_group;" ::: "memory");
    };

    float acc[4][4][4];
#pragma unroll
    for (int a = 0; a < 4; a++)
#pragma unroll
        for (int b = 0; b < 4; b++)
#pragma unroll
            for (int c = 0; c < 4; c++) acc[a][b][c] = 0.f;

    const int warp_m = (wid & 1) * 64;
    const int warp_n = (wid >> 1) * 32;

    load_chunk(0);
    load_chunk(1);

    for (int i = 0; i < NC; i++) {
        asm volatile("cp.async.wait_group 1;" ::: "memory");
        __syncthreads();

        // LO -> HI transition: fold the 2^12 scale out of the accumulators
        if (NPH == 2 && i == KC) {
#pragma unroll
            for (int a = 0; a < 4; a++)
#pragma unroll
                for (int b = 0; b < 4; b++)
#pragma unroll
                    for (int c = 0; c < 4; c++) acc[a][b][c] *= LO_INV;
        }

        uint32_t sA = dataA + (i % NSTAGE)*STAGE_BYTES;
        uint32_t sB = sA + 16384;
#pragma unroll
        for (int ks = 0; ks < 4; ks++) {
            int kb = ks * 32;
            uint32_t af[4][4];
#pragma unroll
            for (int mt = 0; mt < 4; mt++) {
                int rw = warp_m + mt*16 + (lane & 15);
                int cb = kb + ((lane >> 4) << 4);
                ldsm4(af[mt], sA + rw*128 + (cb ^ ((rw & 7) << 4)));
            }
            uint32_t bf[2][4];
#pragma unroll
            for (int nt = 0; nt < 2; nt++) {
                int nr = warp_n + nt*16 + ((lane >> 4) << 3) + (lane & 7);
                int cb = kb + (((lane >> 3) & 1) << 4);
                ldsm4(bf[nt], sB + nr*128 + (cb ^ ((nr & 7) << 4)));
            }
#pragma unroll
            for (int mt = 0; mt < 4; mt++) {
#pragma unroll
                for (int nj = 0; nj < 4; nj++) {
                    const uint32_t* bb = bf[nj >> 1];
                    uint32_t b0 = (nj & 1) ? bb[2] : bb[0];
                    uint32_t b1 = (nj & 1) ? bb[3] : bb[1];
                    mma_f16(acc[mt][nj], af[mt], b0, b1);
                }
            }
        }
        if (i + 2 < NC) load_chunk(i + 2);
        else asm volatile("cp.async.commit_group;" ::: "memory");
    }

    // epilogue
#pragma unroll
    for (int mt = 0; mt < 4; mt++) {
        int row0g = bm + warp_m + mt*16 + (lane >> 2);
#pragma unroll
        for (int nj = 0; nj < 4; nj++) {
            int col = bn + warp_n + nj*8 + (lane & 3)*2;
            float b0 = 0.f, b1 = 0.f;
            if (bias) { b0 = bias[col]; b1 = bias[col+1]; }
            float* p0 = C + (size_t)row0g * N + col;
            float* p1 = C + (size_t)(row0g + 8) * N + col;
            float2 v0 = make_float2(acc[mt][nj][0] + b0, acc[mt][nj][1] + b1);
            float2 v1 = make_float2(acc[mt][nj][2] + b0, acc[mt][nj][3] + b1);
            if (resid) {
                float2 r0 = *(const float2*)(resid + (size_t)row0g * N + col);
                float2 r1 = *(const float2*)(resid + (size_t)(row0g + 8) * N + col);
                v0.x += r0.x; v0.y += r0.y; v1.x += r1.x; v1.y += r1.y;
            }
            *(float2*)p0 = v0;
            *(float2*)p1 = v1;
        }
    }
}

// ------------------------- RoPE (in-place on q,k of qkv) -------------------------
__global__ void rope_kernel(const int* __restrict__ positions, float* __restrict__ qkv) {
    int bs = blockIdx.x;
    int hh = blockIdx.y;
    int i  = threadIdx.x;
    float* base = qkv + (size_t)bs * QKV_DIM + hh * HD;
    float pos = (float)positions[bs];
    float freq = __expf(-(float)i * 0.14391565217f);
    float ang = pos * freq;
    float sn, cs;
    sincosf(ang, &sn, &cs);
    float x1 = base[i];
    float x2 = base[i + 64];
    base[i]      = x1 * cs - x2 * sn;
    base[i + 64] = x2 * cs + x1 * sn;
}

// ------------------------- flash attention (causal, GQA), fp16 ctx out ----
__global__ void __launch_bounds__(128) flash_attn_kernel(
    const float* __restrict__ qkv, __half* __restrict__ ah) {
    __shared__ __align__(16) float Qs[32][HD];
    __shared__ __align__(16) float KVs[32][HD];
    __shared__ float Ss[32][33];
    __shared__ float m_s[32], l_s[32], alpha_s[32];

    int qt = blockIdx.x;
    int h  = blockIdx.y;
    int b  = blockIdx.z;
    int kvh = h >> 4;
    int tid = threadIdx.x;
    int r  = tid >> 2;
    int qd = tid & 3;
    int q0 = qt * 32;

    for (int i = tid; i < 32*32; i += 128) {
        int row = i >> 5, c4 = i & 31;
        ((float4*)Qs[row])[c4] =
            *(const float4*)(qkv + (size_t)(b*SEQ + q0 + row) * QKV_DIM + h*HD + c4*4);
    }
    if (tid < 32) { m_s[tid] = -1e30f; l_s[tid] = 0.f; }
    float acc[32];
#pragma unroll
    for (int i = 0; i < 32; i++) acc[i] = 0.f;
    __syncthreads();

    const float scale = 0.08838834764831845f;

    for (int kt = 0; kt <= qt; kt++) {
        int k0 = kt * 32;
        for (int i = tid; i < 32*32; i += 128) {
            int row = i >> 5, c4 = i & 31;
            ((float4*)KVs[row])[c4] =
                *(const float4*)(qkv + (size_t)(b*SEQ + k0 + row) * QKV_DIM + K_OFF + kvh*HD + c4*4);
        }
        __syncthreads();

        int j0 = qd * 8;
        float sc[8];
#pragma unroll
        for (int jj = 0; jj < 8; jj++) sc[jj] = 0.f;
        const float4* q4 = (const float4*)Qs[r];
#pragma unroll 4
        for (int d4 = 0; d4 < 32; d4++) {
            float4 qv = q4[d4];
#pragma unroll
            for (int jj = 0; jj < 8; jj++) {
                float4 kv = ((const float4*)KVs[j0 + jj])[d4];
                sc[jj] += qv.x*kv.x + qv.y*kv.y + qv.z*kv.z + qv.w*kv.w;
            }
        }
#pragma unroll
        for (int jj = 0; jj < 8; jj++) {
            int kg = k0 + j0 + jj;
            Ss[r][j0 + jj] = (kg <= q0 + r) ? sc[jj] * scale : -1e30f;
        }
        __syncthreads();

        if (tid < 32) {
            float mx = m_s[tid];
            float tm = -1e30f;
#pragma unroll 8
            for (int j = 0; j < 32; j++) tm = fmaxf(tm, Ss[tid][j]);
            float mn = fmaxf(mx, tm);
            float al = __expf(mx - mn);
            float sum = 0.f;
#pragma unroll 8
            for (int j = 0; j < 32; j++) {
                float p = __expf(Ss[tid][j] - mn);
                Ss[tid][j] = p;
                sum += p;
            }
            m_s[tid] = mn;
            l_s[tid] = l_s[tid] * al + sum;
            alpha_s[tid] = al;
        }
        for (int i = tid; i < 32*32; i += 128) {
            int row = i >> 5, c4 = i & 31;
            ((float4*)KVs[row])[c4] =
                *(const float4*)(qkv + (size_t)(b*SEQ + k0 + row) * QKV_DIM + V_OFF + kvh*HD + c4*4);
        }
        __syncthreads();

        float al = alpha_s[r];
#pragma unroll
        for (int i = 0; i < 32; i++) acc[i] *= al;
#pragma unroll 4
        for (int j = 0; j < 32; j++) {
            float p = Ss[r][j];
            const float4* v4 = (const float4*)&KVs[j][qd*32];
#pragma unroll
            for (int i4 = 0; i4 < 8; i4++) {
                float4 vv = v4[i4];
                acc[i4*4+0] = fmaf(p, vv.x, acc[i4*4+0]);
                acc[i4*4+1] = fmaf(p, vv.y, acc[i4*4+1]);
                acc[i4*4+2] = fmaf(p, vv.z, acc[i4*4+2]);
                acc[i4*4+3] = fmaf(p, vv.w, acc[i4*4+3]);
            }
        }
        __syncthreads();
    }

    float invl = 1.f / l_s[r];
    uint2* o2 = (uint2*)(ah + (size_t)(b*SEQ + q0 + r) * HID + h*HD + qd*32);
#pragma unroll
    for (int i4 = 0; i4 < 8; i4++) {
        float4 o = make_float4(acc[i4*4+0]*invl, acc[i4*4+1]*invl,
                               acc[i4*4+2]*invl, acc[i4*4+3]*invl);
        o2[i4] = pack4h(o);
    }
}

// ------------------------- SwiGLU -> fp16 single -------------------------
__global__ void swiglu_h_kernel(const float* __restrict__ inter,
                                __half* __restrict__ gh) {
    int t = blockIdx.x * blockDim.x + threadIdx.x;
    if (t >= M_ROWS * (FFN/4)) return;
    int row = t / (FFN/4);
    int f4  = t - row * (FFN/4);
    const float* irow = inter + (size_t)row * (2*FFN);
    float4 a = *(const float4*)(irow + f4*4);
    float4 b = *(const float4*)(irow + FFN + f4*4);
    float4 o;
    o.x = (a.x / (1.f + __expf(-a.x))) * b.x;
    o.y = (a.y / (1.f + __expf(-a.y))) * b.y;
    o.z = (a.z / (1.f + __expf(-a.z))) * b.z;
    o.w = (a.w / (1.f + __expf(-a.w))) * b.w;
    ((uint2*)(gh + (size_t)row * FFN))[f4] = pack4h(o);
}

// ------------------------- launch -------------------------
extern "C" void kernel_launch(void* const* d_in, const int* in_sizes, int n_in,
                              void* d_out, int out_size) {
    const int*   positions = (const int*)d_in[0];
    const float* hs        = (const float*)d_in[1];
    const float* ln1       = (const float*)d_in[2];
    const float* wqkv      = (const float*)d_in[3];
    const float* bqkv      = (const float*)d_in[4];
    const float* wo        = (const float*)d_in[5];
    const float* ln2       = (const float*)d_in[6];
    const float* w14       = (const float*)d_in[7];
    const float* w41       = (const float*)d_in[8];
    float* out = (float*)d_out;

    float *qkv, *attnout, *hidden, *inter;
    __half *wqkvh, *woh, *w14h, *w41h, *xh, *ah, *yh, *gh;
    cudaGetSymbolAddress((void**)&qkv,     g_qkv);
    cudaGetSymbolAddress((void**)&attnout, g_attnout);
    cudaGetSymbolAddress((void**)&hidden,  g_hidden);
    cudaGetSymbolAddress((void**)&inter,   g_inter);
    cudaGetSymbolAddress((void**)&wqkvh,   g_wqkvh);
    cudaGetSymbolAddress((void**)&woh,     g_woh);
    cudaGetSymbolAddress((void**)&w14h,    g_w14h);
    cudaGetSymbolAddress((void**)&w41h,    g_w41h);
    cudaGetSymbolAddress((void**)&xh,      g_xh);
    cudaGetSymbolAddress((void**)&ah,      g_ah);
    cudaGetSymbolAddress((void**)&yh,      g_yh);
    cudaGetSymbolAddress((void**)&gh,      g_gh);

    cudaFuncSetAttribute(gemm_h<2>, cudaFuncAttributeMaxDynamicSharedMemorySize, GEMM_SMEM);
    cudaFuncSetAttribute(gemm_h<1>, cudaFuncAttributeMaxDynamicSharedMemorySize, GEMM_SMEM);

    // weight conversions
    {
        long long n4;
        n4 = (long long)QKV_DIM * HID / 4;
        split_planar_f16<<<(unsigned)((n4+255)/256), 256>>>(wqkv, wqkvh, n4, HID/4);
        n4 = (long long)HID * HID / 4;
        split_planar_f16<<<(unsigned)((n4+255)/256), 256>>>(wo, woh, n4, HID/4);
        n4 = (long long)(2*FFN) * HID / 4;
        round_f16_kernel<<<(unsigned)((n4+255)/256), 256>>>(w14, w14h, n4);
        n4 = (long long)HID * FFN / 4;
        round_f16_kernel<<<(unsigned)((n4+255)/256), 256>>>(w41, w41h, n4);
    }

    // 1) xh = f16(rmsnorm(hs) * ln1)
    fused_norm_kernel<<<M_ROWS, 256>>>(nullptr, hs, ln1, nullptr, xh);

    // 2) qkv = x @ wqkv^T + bqkv   (2-phase exact weights)
    gemm_h<2><<<16*36, 256, GEMM_SMEM>>>(xh, wqkvh, bqkv, nullptr, qkv, 36, HID, QKV_DIM);

    // 3) rope on q,k
    rope_kernel<<<dim3(M_ROWS, NH + NKV), 64>>>(positions, qkv);

    // 4) attention -> ah (fp16 ctx)
    flash_attn_kernel<<<dim3(SEQ/32, NH, BATCH), 128>>>(qkv, ah);

    // 5) attn_out = ctx @ wo^T   (2-phase exact weights)
    gemm_h<2><<<16*32, 256, GEMM_SMEM>>>(ah, woh, nullptr, nullptr, attnout, 32, HID, HID);

    // 6) hidden = hs + attn_out ; yh = f16(rmsnorm(hidden) * ln2)
    fused_norm_kernel<<<M_ROWS, 256>>>(hs, attnout, ln2, hidden, yh);

    // 7) inter = y @ w14^T   (1-phase fp16 weights)
    gemm_h<1><<<16*214, 256, GEMM_SMEM>>>(yh, w14h, nullptr, nullptr, inter, 214, HID, 2*FFN);

    // 8) gh = f16(silu(a)*b)
    swiglu_h_kernel<<<(M_ROWS*(FFN/4) + 255)/256, 256>>>(inter, gh);

    // 9) out = hidden + gated @ w41^T   (1-phase fp16 weights, residual fused)
    gemm_h<1><<<16*32, 256, GEMM_SMEM>>>(gh, w41h, nullptr, hidden, out, 32, FFN, HID);
}